// round 9
// baseline (speedup 1.0000x reference)
#include <cuda_runtime.h>
#include <cuda_fp16.h>
#include <stdint.h>

#define NN 100000
#define NE 3200000
#define F  16
#define PAD 128            // fixed bucket size; P(deg > 128) ~ 17-sigma ~ 0
#define NBLK ((NN + 255) / 256)

// Scratch (allocation-free rule: __device__ globals)
__device__ __align__(16) int    d_deg[NN];
__device__ __align__(16) int    d_csr[NN * PAD];   // 51.2 MB padded buckets (512B rows)
__device__ __align__(16) float  d_dis[NN];
__device__ __align__(16) __half d_g16[NN * F];     // fp16 messages (32B rows)
__device__ __align__(16) float  d_acc[NN * F];     // fp32 accumulator / seed

__global__ void k_zero() {
    int i = blockIdx.x * blockDim.x + threadIdx.x;
    if (i < NN) d_deg[i] = 0;
}

// Single-pass CSR build (4 edges/thread): off = atomicAdd(deg[dst]); csr[dst*128+off] = src
__global__ void k_build(const int* __restrict__ ei) {
    int t = blockIdx.x * blockDim.x + threadIdx.x;
    if (t >= NE / 4) return;
    int4 s4 = ((const int4*)ei)[t];
    int4 d4 = ((const int4*)(ei + NE))[t];
    int o0 = atomicAdd(&d_deg[d4.x], 1);
    int o1 = atomicAdd(&d_deg[d4.y], 1);
    int o2 = atomicAdd(&d_deg[d4.z], 1);
    int o3 = atomicAdd(&d_deg[d4.w], 1);
    d_csr[(d4.x << 7) + o0] = s4.x;
    d_csr[(d4.y << 7) + o1] = s4.y;
    d_csr[(d4.z << 7) + o2] = s4.z;
    d_csr[(d4.w << 7) + o3] = s4.w;
}

__device__ __forceinline__ void store_row(int i, const float* h) {
    // fp32 seed for the accumulator + fp16 message row
    float4* ap = (float4*)(d_acc + (size_t)i * F);
#pragma unroll
    for (int p = 0; p < 4; p++)
        ap[p] = make_float4(h[p * 4 + 0], h[p * 4 + 1], h[p * 4 + 2], h[p * 4 + 3]);
    __half2* gp = (__half2*)(d_g16 + (size_t)i * F);
#pragma unroll
    for (int p = 0; p < 8; p++)
        gp[p] = __floats2half2_rn(h[p * 2 + 0], h[p * 2 + 1]);
}

// Layer-1 init: dis = rsqrt(deg+1); g = dis * (x@W1); acc seed = g (fp32)
__global__ void k_l1_init(const float* __restrict__ x, const float* __restrict__ W1) {
    __shared__ float sW[F * F];
    int t = threadIdx.x;
    if (t < F * F) sW[t] = W1[t];
    __syncthreads();
    int i = blockIdx.x * blockDim.x + t;
    if (i >= NN) return;

    float dis = rsqrtf((float)(d_deg[i] + 1));
    d_dis[i] = dis;

    float xi[F];
    const float4* xr = (const float4*)(x + (size_t)i * F);
#pragma unroll
    for (int q = 0; q < 4; q++) {
        float4 v = xr[q];
        xi[q * 4 + 0] = v.x; xi[q * 4 + 1] = v.y;
        xi[q * 4 + 2] = v.z; xi[q * 4 + 3] = v.w;
    }
    float h[F];
#pragma unroll
    for (int j = 0; j < F; j++) {
        float a = 0.f;
#pragma unroll
        for (int k = 0; k < F; k++) a = fmaf(xi[k], sW[k * F + j], a);
        h[j] = a * dis;
    }
    store_row(i, h);
}

// Gather: thread = (node w, half-row q in {0,1}); 8 fp32 accumulators.
// Indices as int4 (4 edges / LDG.128) -> 4 independent 16B fp16 gathers.
__global__ void k_gather() {
    int tid = blockIdx.x * blockDim.x + threadIdx.x;
    if (tid >= NN * 2) return;
    int w = tid >> 1;
    int q = tid & 1;

    const uint4* __restrict__ G = (const uint4*)d_g16;  // 16B = 8 halfs per (node,q)
    float acc[8];
    {   // fp32 seed (self-loop, exact)
        const float4* A = (const float4*)d_acc;
        float4 s0 = A[w * 4 + q * 2 + 0];
        float4 s1 = A[w * 4 + q * 2 + 1];
        acc[0] = s0.x; acc[1] = s0.y; acc[2] = s0.z; acc[3] = s0.w;
        acc[4] = s1.x; acc[5] = s1.y; acc[6] = s1.z; acc[7] = s1.w;
    }
    int deg = d_deg[w];
    const int4* __restrict__ idx4 = (const int4*)(d_csr + (w << 7));

#define ACC_H(vv)                                                       \
    {                                                                   \
        const __half2* hp = (const __half2*)&(vv);                      \
        float2 f0 = __half22float2(hp[0]);                              \
        float2 f1 = __half22float2(hp[1]);                              \
        float2 f2 = __half22float2(hp[2]);                              \
        float2 f3 = __half22float2(hp[3]);                              \
        acc[0] += f0.x; acc[1] += f0.y; acc[2] += f1.x; acc[3] += f1.y; \
        acc[4] += f2.x; acc[5] += f2.y; acc[6] += f3.x; acc[7] += f3.y; \
    }

    int full = deg >> 2;
    for (int k = 0; k < full; k++) {
        int4 s = idx4[k];
        uint4 v0 = G[s.x * 2 + q];
        uint4 v1 = G[s.y * 2 + q];
        uint4 v2 = G[s.z * 2 + q];
        uint4 v3 = G[s.w * 2 + q];
        ACC_H(v0); ACC_H(v1); ACC_H(v2); ACC_H(v3);
    }
    const int* __restrict__ rp = d_csr + (w << 7) + (full << 2);
    int rem = deg & 3;
    for (int r = 0; r < rem; r++) {
        uint4 v = G[rp[r] * 2 + q];
        ACC_H(v);
    }
#undef ACC_H

    float4* A = (float4*)d_acc;
    A[w * 4 + q * 2 + 0] = make_float4(acc[0], acc[1], acc[2], acc[3]);
    A[w * 4 + q * 2 + 1] = make_float4(acc[4], acc[5], acc[6], acc[7]);
}

// Finalize layer 1 + start layer 2: h1 = relu(dis*acc + b1); g2 = dis*(h1@W2);
// writes fp32 seed + fp16 messages
__global__ void k_mid(const float* __restrict__ b1, const float* __restrict__ W2) {
    __shared__ float sW[F * F];
    __shared__ float sb[F];
    int t = threadIdx.x;
    if (t < F * F) sW[t] = W2[t];
    if (t < F) sb[t] = b1[t];
    __syncthreads();
    int i = blockIdx.x * blockDim.x + t;
    if (i >= NN) return;

    float dis = d_dis[i];
    float h1[F];
    const float4* ar = (const float4*)(d_acc + (size_t)i * F);
#pragma unroll
    for (int p = 0; p < 4; p++) {
        float4 v = ar[p];
        h1[p * 4 + 0] = fmaxf(fmaf(dis, v.x, sb[p * 4 + 0]), 0.f);
        h1[p * 4 + 1] = fmaxf(fmaf(dis, v.y, sb[p * 4 + 1]), 0.f);
        h1[p * 4 + 2] = fmaxf(fmaf(dis, v.z, sb[p * 4 + 2]), 0.f);
        h1[p * 4 + 3] = fmaxf(fmaf(dis, v.w, sb[p * 4 + 3]), 0.f);
    }
    float h2[F];
#pragma unroll
    for (int j = 0; j < F; j++) {
        float s = 0.f;
#pragma unroll
        for (int k = 0; k < F; k++) s = fmaf(h1[k], sW[k * F + j], s);
        h2[j] = s * dis;
    }
    store_row(i, h2);
}

// Finalize layer 2 + FC head: out[i] = relu(dis*acc + b2) . Wfc + bfc
__global__ void k_final(const float* __restrict__ b2, const float* __restrict__ Wfc,
                        const float* __restrict__ bfc, float* __restrict__ out) {
    __shared__ float sb[F];
    __shared__ float sw[F];
    __shared__ float sbias;
    int t = threadIdx.x;
    if (t < F) { sb[t] = b2[t]; sw[t] = Wfc[t]; }
    if (t == 0) sbias = bfc[0];
    __syncthreads();
    int i = blockIdx.x * blockDim.x + t;
    if (i >= NN) return;

    float dis = d_dis[i];
    float a = 0.f;
    const float4* ar = (const float4*)(d_acc + (size_t)i * F);
#pragma unroll
    for (int p = 0; p < 4; p++) {
        float4 v = ar[p];
        a = fmaf(fmaxf(fmaf(dis, v.x, sb[p * 4 + 0]), 0.f), sw[p * 4 + 0], a);
        a = fmaf(fmaxf(fmaf(dis, v.y, sb[p * 4 + 1]), 0.f), sw[p * 4 + 1], a);
        a = fmaf(fmaxf(fmaf(dis, v.z, sb[p * 4 + 2]), 0.f), sw[p * 4 + 2], a);
        a = fmaf(fmaxf(fmaf(dis, v.w, sb[p * 4 + 3]), 0.f), sw[p * 4 + 3], a);
    }
    out[i] = a + sbias;
}

extern "C" void kernel_launch(void* const* d_in, const int* in_sizes, int n_in,
                              void* d_out, int out_size) {
    const float* x   = (const float*)d_in[0];
    const int*   ei  = (const int*)d_in[1];     // int32 (JAX x64 disabled)
    const float* W1  = (const float*)d_in[2];
    const float* b1  = (const float*)d_in[3];
    const float* W2  = (const float*)d_in[4];
    const float* b2  = (const float*)d_in[5];
    const float* Wfc = (const float*)d_in[6];
    const float* bfc = (const float*)d_in[7];
    float* out = (float*)d_out;

    const int TB = 256;
    const int nodeBlocks   = NBLK;
    const int edge4Blocks  = (NE / 4 + TB - 1) / TB;
    const int gatherBlocks = (NN * 2 + TB - 1) / TB;

    k_zero<<<nodeBlocks, TB>>>();
    k_build<<<edge4Blocks, TB>>>(ei);
    k_l1_init<<<nodeBlocks, TB>>>(x, W1);
    k_gather<<<gatherBlocks, TB>>>();
    k_mid<<<nodeBlocks, TB>>>(b1, W2);
    k_gather<<<gatherBlocks, TB>>>();
    k_final<<<nodeBlocks, TB>>>(b2, Wfc, bfc, out);
}

// round 10
// speedup vs baseline: 1.4102x; 1.4102x over previous
#include <cuda_runtime.h>
#include <stdint.h>

#define NN 100000
#define NE 3200000
#define F  16
#define PAD 128            // fixed bucket size; P(deg > 128) ~ 17-sigma ~ 0
#define NBLK ((NN + 255) / 256)

// Scratch (allocation-free rule: __device__ globals)
__device__ __align__(16) int   d_deg[NN];
__device__ __align__(16) int   d_csr[NN * PAD];   // padded buckets, 512B-aligned rows
__device__ __align__(16) float d_dis[NN];
__device__ __align__(16) float d_g[NN * F];
__device__ __align__(16) float d_acc[NN * F];

__global__ void k_zero() {
    int i = blockIdx.x * blockDim.x + threadIdx.x;
    if (i < NN) d_deg[i] = 0;
}

// Single-pass CSR build, 8 edges/thread: off = atomicAdd(deg[dst]); csr[dst*128+off] = src
__global__ void k_build(const int* __restrict__ ei) {
    int t = blockIdx.x * blockDim.x + threadIdx.x;
    if (t >= NE / 8) return;
    const int4* S = (const int4*)ei;
    const int4* D = (const int4*)(ei + NE);
    int4 sa = S[t * 2], sb = S[t * 2 + 1];
    int4 da = D[t * 2], db = D[t * 2 + 1];
    int oa0 = atomicAdd(&d_deg[da.x], 1);
    int oa1 = atomicAdd(&d_deg[da.y], 1);
    int oa2 = atomicAdd(&d_deg[da.z], 1);
    int oa3 = atomicAdd(&d_deg[da.w], 1);
    int ob0 = atomicAdd(&d_deg[db.x], 1);
    int ob1 = atomicAdd(&d_deg[db.y], 1);
    int ob2 = atomicAdd(&d_deg[db.z], 1);
    int ob3 = atomicAdd(&d_deg[db.w], 1);
    d_csr[(da.x << 7) + oa0] = sa.x;
    d_csr[(da.y << 7) + oa1] = sa.y;
    d_csr[(da.z << 7) + oa2] = sa.z;
    d_csr[(da.w << 7) + oa3] = sa.w;
    d_csr[(db.x << 7) + ob0] = sb.x;
    d_csr[(db.y << 7) + ob1] = sb.y;
    d_csr[(db.z << 7) + ob2] = sb.z;
    d_csr[(db.w << 7) + ob3] = sb.w;
}

// Layer-1 init: dis = rsqrt(deg+1); g = dis * (x@W1)
__global__ void k_l1_init(const float* __restrict__ x, const float* __restrict__ W1) {
    __shared__ float sW[F * F];
    int t = threadIdx.x;
    if (t < F * F) sW[t] = W1[t];
    __syncthreads();
    int i = blockIdx.x * blockDim.x + t;
    if (i >= NN) return;

    float dis = rsqrtf((float)(d_deg[i] + 1));
    d_dis[i] = dis;

    float xi[F];
    const float4* xr = (const float4*)(x + (size_t)i * F);
#pragma unroll
    for (int q = 0; q < 4; q++) {
        float4 v = xr[q];
        xi[q * 4 + 0] = v.x; xi[q * 4 + 1] = v.y;
        xi[q * 4 + 2] = v.z; xi[q * 4 + 3] = v.w;
    }
    float4* gp = (float4*)(d_g + (size_t)i * F);
#pragma unroll
    for (int q = 0; q < 4; q++) {
        float4 h;
        float* hp = &h.x;
#pragma unroll
        for (int jj = 0; jj < 4; jj++) {
            int j = q * 4 + jj;
            float a = 0.f;
#pragma unroll
            for (int k = 0; k < F; k++) a = fmaf(xi[k], sW[k * F + j], a);
            hp[jj] = a * dis;
        }
        gp[q] = h;
    }
}

// Gather: thread = (node w, chunk q). Index stream read as int4 (4 edges/LDG.128),
// unrolled x2 so 2 idx loads + 8 feature gathers are in flight per iteration.
__global__ void k_gather() {
    int tid = blockIdx.x * blockDim.x + threadIdx.x;
    if (tid >= NN * 4) return;
    int w = tid >> 2;
    int q = tid & 3;

    const float4* __restrict__ G = (const float4*)d_g;
    float4 a = G[w * 4 + q];            // self-loop (independent, issued early)
    float4 b = make_float4(0.f, 0.f, 0.f, 0.f);
    int deg = d_deg[w];

    const int4* __restrict__ idx4 = (const int4*)(d_csr + (w << 7));
    int full = deg >> 2;                // int4 groups
    int k = 0;
    for (; k + 1 < full; k += 2) {
        int4 s0 = idx4[k];
        int4 s1 = idx4[k + 1];
        float4 v0 = G[s0.x * 4 + q];
        float4 v1 = G[s0.y * 4 + q];
        float4 v2 = G[s0.z * 4 + q];
        float4 v3 = G[s0.w * 4 + q];
        float4 u0 = G[s1.x * 4 + q];
        float4 u1 = G[s1.y * 4 + q];
        float4 u2 = G[s1.z * 4 + q];
        float4 u3 = G[s1.w * 4 + q];
        a.x += (v0.x + v1.x) + (v2.x + v3.x);
        a.y += (v0.y + v1.y) + (v2.y + v3.y);
        a.z += (v0.z + v1.z) + (v2.z + v3.z);
        a.w += (v0.w + v1.w) + (v2.w + v3.w);
        b.x += (u0.x + u1.x) + (u2.x + u3.x);
        b.y += (u0.y + u1.y) + (u2.y + u3.y);
        b.z += (u0.z + u1.z) + (u2.z + u3.z);
        b.w += (u0.w + u1.w) + (u2.w + u3.w);
    }
    if (k < full) {
        int4 s = idx4[k];
        float4 v0 = G[s.x * 4 + q];
        float4 v1 = G[s.y * 4 + q];
        float4 v2 = G[s.z * 4 + q];
        float4 v3 = G[s.w * 4 + q];
        a.x += (v0.x + v1.x) + (v2.x + v3.x);
        a.y += (v0.y + v1.y) + (v2.y + v3.y);
        a.z += (v0.z + v1.z) + (v2.z + v3.z);
        a.w += (v0.w + v1.w) + (v2.w + v3.w);
    }
    const int* __restrict__ rp = d_csr + (w << 7) + (full << 2);
    int rem = deg & 3;
    for (int r = 0; r < rem; r++) {
        float4 v = G[rp[r] * 4 + q];
        a.x += v.x; a.y += v.y; a.z += v.z; a.w += v.w;
    }
    a.x += b.x; a.y += b.y; a.z += b.z; a.w += b.w;
    ((float4*)d_acc)[w * 4 + q] = a;
}

// Finalize layer 1 + start layer 2: h1 = relu(dis*acc + b1); g = dis*(h1@W2)
__global__ void k_mid(const float* __restrict__ b1, const float* __restrict__ W2) {
    __shared__ float sW[F * F];
    __shared__ float sb[F];
    int t = threadIdx.x;
    if (t < F * F) sW[t] = W2[t];
    if (t < F) sb[t] = b1[t];
    __syncthreads();
    int i = blockIdx.x * blockDim.x + t;
    if (i >= NN) return;

    float dis = d_dis[i];
    float h1[F];
    const float4* ar = (const float4*)(d_acc + (size_t)i * F);
#pragma unroll
    for (int p = 0; p < 4; p++) {
        float4 v = ar[p];
        h1[p * 4 + 0] = fmaxf(fmaf(dis, v.x, sb[p * 4 + 0]), 0.f);
        h1[p * 4 + 1] = fmaxf(fmaf(dis, v.y, sb[p * 4 + 1]), 0.f);
        h1[p * 4 + 2] = fmaxf(fmaf(dis, v.z, sb[p * 4 + 2]), 0.f);
        h1[p * 4 + 3] = fmaxf(fmaf(dis, v.w, sb[p * 4 + 3]), 0.f);
    }
    float4* gp = (float4*)(d_g + (size_t)i * F);
#pragma unroll
    for (int p = 0; p < 4; p++) {
        float4 h2;
        float* hp = &h2.x;
#pragma unroll
        for (int jj = 0; jj < 4; jj++) {
            int col = p * 4 + jj;
            float s = 0.f;
#pragma unroll
            for (int k = 0; k < F; k++) s = fmaf(h1[k], sW[k * F + col], s);
            hp[jj] = s * dis;
        }
        gp[p] = h2;
    }
}

// Finalize layer 2 + FC head: out[i] = relu(dis*acc + b2) . Wfc + bfc
__global__ void k_final(const float* __restrict__ b2, const float* __restrict__ Wfc,
                        const float* __restrict__ bfc, float* __restrict__ out) {
    __shared__ float sb[F];
    __shared__ float sw[F];
    __shared__ float sbias;
    int t = threadIdx.x;
    if (t < F) { sb[t] = b2[t]; sw[t] = Wfc[t]; }
    if (t == 0) sbias = bfc[0];
    __syncthreads();
    int i = blockIdx.x * blockDim.x + t;
    if (i >= NN) return;

    float dis = d_dis[i];
    float a = 0.f;
    const float4* ar = (const float4*)(d_acc + (size_t)i * F);
#pragma unroll
    for (int p = 0; p < 4; p++) {
        float4 v = ar[p];
        a = fmaf(fmaxf(fmaf(dis, v.x, sb[p * 4 + 0]), 0.f), sw[p * 4 + 0], a);
        a = fmaf(fmaxf(fmaf(dis, v.y, sb[p * 4 + 1]), 0.f), sw[p * 4 + 1], a);
        a = fmaf(fmaxf(fmaf(dis, v.z, sb[p * 4 + 2]), 0.f), sw[p * 4 + 2], a);
        a = fmaf(fmaxf(fmaf(dis, v.w, sb[p * 4 + 3]), 0.f), sw[p * 4 + 3], a);
    }
    out[i] = a + sbias;
}

extern "C" void kernel_launch(void* const* d_in, const int* in_sizes, int n_in,
                              void* d_out, int out_size) {
    const float* x   = (const float*)d_in[0];
    const int*   ei  = (const int*)d_in[1];     // int32 (JAX x64 disabled)
    const float* W1  = (const float*)d_in[2];
    const float* b1  = (const float*)d_in[3];
    const float* W2  = (const float*)d_in[4];
    const float* b2  = (const float*)d_in[5];
    const float* Wfc = (const float*)d_in[6];
    const float* bfc = (const float*)d_in[7];
    float* out = (float*)d_out;

    const int TB = 256;
    const int nodeBlocks   = NBLK;
    const int edge8Blocks  = (NE / 8 + TB - 1) / TB;
    const int gatherBlocks = (NN * 4 + TB - 1) / TB;

    k_zero<<<nodeBlocks, TB>>>();
    k_build<<<edge8Blocks, TB>>>(ei);
    k_l1_init<<<nodeBlocks, TB>>>(x, W1);
    k_gather<<<gatherBlocks, TB>>>();
    k_mid<<<nodeBlocks, TB>>>(b1, W2);
    k_gather<<<gatherBlocks, TB>>>();
    k_final<<<nodeBlocks, TB>>>(b2, Wfc, bfc, out);
}